// round 1
// baseline (speedup 1.0000x reference)
#include <cuda_runtime.h>
#include <math.h>

// ---------------- problem constants ----------------
#define B_    4
#define NP_   512
#define PS_   16
#define D_    1024
#define NH_   4
#define HD_   256
#define PH_   4
#define PHD_  256
#define KW_   5
#define T_    (B_*NP_*PS_)        // 32768 tokens
#define P_    (B_*NP_)            // 2048 patches
#define EPS_  1.1920929e-7f       // finfo(float32).eps

// ---------------- device scratch (allocation-free rule: __device__ globals) ----
__device__ float g_x  [(size_t)T_*D_];   // residual stream
__device__ float g_xn [(size_t)T_*D_];   // normalized
__device__ float g_t1 [(size_t)T_*D_];
__device__ float g_t2 [(size_t)T_*D_];
__device__ float g_qkv[(size_t)T_*3*D_];
__device__ float g_p0 [(size_t)P_*D_];   // pooled
__device__ float g_p1 [(size_t)P_*D_];
__device__ float g_p2 [(size_t)P_*D_];

// ---------------- reductions ----------------
__device__ __forceinline__ float warp_sum(float v) {
#pragma unroll
    for (int o = 16; o; o >>= 1) v += __shfl_down_sync(0xffffffffu, v, o);
    return v;
}

__device__ __forceinline__ float block_sum_256(float v, float* red) {
    int lane = threadIdx.x & 31, w = threadIdx.x >> 5;
    v = warp_sum(v);
    if (lane == 0) red[w] = v;
    __syncthreads();
    if (w == 0) {
        float x = (lane < 8) ? red[lane] : 0.f;
        x = warp_sum(x);
        if (lane == 0) red[0] = x;
    }
    __syncthreads();
    return red[0];
}

// ---------------- norm kernels (one block per row of 1024) ----------------
__global__ void k_add_pos_norm(const float* __restrict__ x,
                               const float* __restrict__ pos,
                               float* __restrict__ out) {
    __shared__ float red[8];
    int row = blockIdx.x, t = threadIdx.x;
    const float4* xr = (const float4*)(x + (size_t)row * D_);
    const float4* pr = (const float4*)(pos + (size_t)(row & (PS_-1)) * D_);
    float4 a = xr[t], b = pr[t];
    a.x += b.x; a.y += b.y; a.z += b.z; a.w += b.w;
    float ss = a.x*a.x + a.y*a.y + a.z*a.z + a.w*a.w;
    float tot = block_sum_256(ss, red);
    float s = rsqrtf(tot * (1.0f/D_) + EPS_);
    float4 o = make_float4(a.x*s, a.y*s, a.z*s, a.w*s);
    ((float4*)(out + (size_t)row * D_))[t] = o;
}

__global__ void k_rmsnorm(const float* __restrict__ x, float* __restrict__ out) {
    __shared__ float red[8];
    int row = blockIdx.x, t = threadIdx.x;
    float4 a = ((const float4*)(x + (size_t)row * D_))[t];
    float ss = a.x*a.x + a.y*a.y + a.z*a.z + a.w*a.w;
    float tot = block_sum_256(ss, red);
    float s = rsqrtf(tot * (1.0f/D_) + EPS_);
    float4 o = make_float4(a.x*s, a.y*s, a.z*s, a.w*s);
    ((float4*)(out + (size_t)row * D_))[t] = o;
}

// out = rmsnorm(a + b)
__global__ void k_add_norm(const float* __restrict__ a,
                           const float* __restrict__ b,
                           float* __restrict__ out) {
    __shared__ float red[8];
    int row = blockIdx.x, t = threadIdx.x;
    float4 va = ((const float4*)(a + (size_t)row * D_))[t];
    float4 vb = ((const float4*)(b + (size_t)row * D_))[t];
    va.x += vb.x; va.y += vb.y; va.z += vb.z; va.w += vb.w;
    float ss = va.x*va.x + va.y*va.y + va.z*va.z + va.w*va.w;
    float tot = block_sum_256(ss, red);
    float s = rsqrtf(tot * (1.0f/D_) + EPS_);
    float4 o = make_float4(va.x*s, va.y*s, va.z*s, va.w*s);
    ((float4*)(out + (size_t)row * D_))[t] = o;
}

// ---------------- elementwise: out = silu(g) * u ----------------
__global__ void k_silu_mul(const float* __restrict__ g,
                           const float* __restrict__ u,
                           float* __restrict__ out, int n4) {
    int i = blockIdx.x * blockDim.x + threadIdx.x;
    if (i >= n4) return;
    float4 a = ((const float4*)g)[i];
    float4 b = ((const float4*)u)[i];
    a.x = a.x / (1.f + __expf(-a.x)) * b.x;
    a.y = a.y / (1.f + __expf(-a.y)) * b.y;
    a.z = a.z / (1.f + __expf(-a.z)) * b.z;
    a.w = a.w / (1.f + __expf(-a.w)) * b.w;
    ((float4*)out)[i] = a;
}

// ---------------- depthwise causal conv (K=5) + residual, in place ----------
__global__ void k_conv(float* __restrict__ x, const float* __restrict__ w) {
    int patch = blockIdx.x;
    int c = blockIdx.y * blockDim.x + threadIdx.x;
    float wk[KW_];
#pragma unroll
    for (int k = 0; k < KW_; k++) wk[k] = w[c * KW_ + k];
    size_t base = (size_t)patch * PS_ * D_ + c;
    float v[PS_];
#pragma unroll
    for (int p = 0; p < PS_; p++) v[p] = x[base + (size_t)p * D_];
#pragma unroll
    for (int p = 0; p < PS_; p++) {
        float acc = v[p];
#pragma unroll
        for (int k = 0; k < KW_; k++) {
            int src = p + k - (KW_ - 1);
            if (src >= 0) acc += v[src] * wk[k];
        }
        x[base + (size_t)p * D_] = acc;
    }
}

// ---------------- intra-patch attention: block per (patch, head) ----------
__global__ void k_attn(const float* __restrict__ qkv, float* __restrict__ sa) {
    __shared__ float bufA[PS_ * HD_];          // q, then v
    __shared__ float bufK[HD_ * (PS_ + 1)];    // k transposed, padded
    __shared__ float S[PS_][PS_ + 1];
    int patch = blockIdx.x, h = blockIdx.y, t = threadIdx.x;

    for (int i = t; i < PS_ * HD_; i += 256) {
        int p = i >> 8, d = i & (HD_ - 1);
        size_t base = ((size_t)(patch * PS_ + p)) * (3 * D_) + (size_t)h * HD_;
        bufA[p * HD_ + d] = qkv[base + d];            // q
        bufK[d * (PS_ + 1) + p] = qkv[base + D_ + d]; // k^T
    }
    __syncthreads();

    {   // scores
        int i = t >> 4, j = t & 15;
        float acc = 0.f;
#pragma unroll 8
        for (int d = 0; d < HD_; d++)
            acc += bufA[i * HD_ + d] * bufK[d * (PS_ + 1) + j];
        S[i][j] = acc * 0.0625f;   // HD^-0.5 = 1/16
    }
    __syncthreads();

    // load v (overwrites q, safe after sync); softmax by first 16 threads
    for (int i = t; i < PS_ * HD_; i += 256) {
        int p = i >> 8, d = i & (HD_ - 1);
        size_t base = ((size_t)(patch * PS_ + p)) * (3 * D_) + (size_t)h * HD_;
        bufA[p * HD_ + d] = qkv[base + 2 * D_ + d];
    }
    if (t < PS_) {
        float lv[PS_], m = -1e30f;
#pragma unroll
        for (int j = 0; j < PS_; j++) { lv[j] = S[t][j]; m = fmaxf(m, lv[j]); }
        float s = 0.f;
#pragma unroll
        for (int j = 0; j < PS_; j++) { lv[j] = __expf(lv[j] - m); s += lv[j]; }
        float inv = 1.f / s;
#pragma unroll
        for (int j = 0; j < PS_; j++) S[t][j] = lv[j] * inv;
    }
    __syncthreads();

    {   // PV
        int i = t >> 4, dc = t & 15;
        float acc[16];
#pragma unroll
        for (int r = 0; r < 16; r++) acc[r] = 0.f;
#pragma unroll
        for (int j = 0; j < PS_; j++) {
            float s = S[i][j];
#pragma unroll
            for (int r = 0; r < 16; r++)
                acc[r] += s * bufA[j * HD_ + dc + (r << 4)];
        }
        size_t ob = ((size_t)(patch * PS_ + i)) * D_ + (size_t)h * HD_ + dc;
#pragma unroll
        for (int r = 0; r < 16; r++) sa[ob + (r << 4)] = acc[r];
    }
}

// ---------------- attention pooling: block per patch ----------------
__global__ void k_pool(const float* __restrict__ x5,
                       const float* __restrict__ wpool,
                       const float* __restrict__ temp,
                       float* __restrict__ out) {
    __shared__ float swp[PH_ * D_];
    __shared__ float slog[PH_][PS_];
    int patch = blockIdx.x, t = threadIdx.x;
    for (int i = t; i < PH_ * D_; i += 256) swp[i] = wpool[i];
    __syncthreads();

    int w = t >> 5, lane = t & 31;
    for (int p = w; p < PS_; p += 8) {
        const float* xr = x5 + ((size_t)patch * PS_ + p) * D_;
        float a0 = 0, a1 = 0, a2 = 0, a3 = 0;
        for (int d = lane; d < D_; d += 32) {
            float xv = xr[d];
            a0 += xv * swp[d];
            a1 += xv * swp[D_ + d];
            a2 += xv * swp[2 * D_ + d];
            a3 += xv * swp[3 * D_ + d];
        }
        a0 = warp_sum(a0); a1 = warp_sum(a1); a2 = warp_sum(a2); a3 = warp_sum(a3);
        if (lane == 0) { slog[0][p] = a0; slog[1][p] = a1; slog[2][p] = a2; slog[3][p] = a3; }
    }
    __syncthreads();

    if (t < PH_) {
        float inv = 1.f / fmaxf(temp[0], 0.01f);
        float lv[PS_], m = -1e30f;
#pragma unroll
        for (int p = 0; p < PS_; p++) { lv[p] = slog[t][p] * inv; m = fmaxf(m, lv[p]); }
        float s = 0.f;
#pragma unroll
        for (int p = 0; p < PS_; p++) { lv[p] = __expf(lv[p] - m); s += lv[p]; }
        float is = 1.f / s;
#pragma unroll
        for (int p = 0; p < PS_; p++) slog[t][p] = lv[p] * is;
    }
    __syncthreads();

    int dd = t * 4;
    int h = dd >> 8;    // PHD = 256
    float4 acc = make_float4(0, 0, 0, 0);
#pragma unroll
    for (int p = 0; p < PS_; p++) {
        float wg = slog[h][p];
        float4 xv = *(const float4*)(x5 + ((size_t)patch * PS_ + p) * D_ + dd);
        acc.x += wg * xv.x; acc.y += wg * xv.y; acc.z += wg * xv.z; acc.w += wg * xv.w;
    }
    *(float4*)(out + (size_t)patch * D_ + dd) = acc;
}

// ---------------- SGEMM: C[M,N] = A[M,K] * Bw[N,K]^T (NT), fp32 -------------
// EPI: 0=store, 1=silu(store), 2=store + aux
template <int EPI>
__global__ __launch_bounds__(256)
void sgemm_nt(int M, int N, int Kd,
              const float* __restrict__ A,
              const float* __restrict__ Bw,
              const float* __restrict__ aux,
              float* __restrict__ C) {
    constexpr int BM = 128, BN = 128, BK = 8, TM = 8, TN = 8;
    __shared__ float As[2][BK][BM];
    __shared__ float Bs[2][BK][BN];
    int tid = threadIdx.x;
    int bx = blockIdx.x;   // N tile
    int by = blockIdx.y;   // M tile

    const int loadRow = tid >> 1;
    const int loadCol = (tid & 1) * 4;
    const float* Ag = A  + (size_t)(by * BM + loadRow) * Kd + loadCol;
    const float* Bg = Bw + (size_t)(bx * BN + loadRow) * Kd + loadCol;

    float acc[TM][TN];
#pragma unroll
    for (int i = 0; i < TM; i++)
#pragma unroll
        for (int j = 0; j < TN; j++) acc[i][j] = 0.f;

    const int nk = Kd / BK;

    {   // prologue: tile 0 -> buffer 0
        float4 a = *(const float4*)Ag;
        float4 b = *(const float4*)Bg;
        As[0][loadCol + 0][loadRow] = a.x; As[0][loadCol + 1][loadRow] = a.y;
        As[0][loadCol + 2][loadRow] = a.z; As[0][loadCol + 3][loadRow] = a.w;
        Bs[0][loadCol + 0][loadRow] = b.x; Bs[0][loadCol + 1][loadRow] = b.y;
        Bs[0][loadCol + 2][loadRow] = b.z; Bs[0][loadCol + 3][loadRow] = b.w;
    }
    __syncthreads();

    const int tr = (tid >> 4) * TM;
    const int tc = (tid & 15) * TN;

    for (int kt = 0; kt < nk; kt++) {
        int cur = kt & 1, nxt = cur ^ 1;
        if (kt + 1 < nk) {
            float4 a = *(const float4*)(Ag + (size_t)(kt + 1) * BK);
            float4 b = *(const float4*)(Bg + (size_t)(kt + 1) * BK);
            As[nxt][loadCol + 0][loadRow] = a.x; As[nxt][loadCol + 1][loadRow] = a.y;
            As[nxt][loadCol + 2][loadRow] = a.z; As[nxt][loadCol + 3][loadRow] = a.w;
            Bs[nxt][loadCol + 0][loadRow] = b.x; Bs[nxt][loadCol + 1][loadRow] = b.y;
            Bs[nxt][loadCol + 2][loadRow] = b.z; Bs[nxt][loadCol + 3][loadRow] = b.w;
        }
#pragma unroll
        for (int k = 0; k < BK; k++) {
            float rm[TM], rn[TN];
#pragma unroll
            for (int i = 0; i < TM; i++) rm[i] = As[cur][k][tr + i];
#pragma unroll
            for (int j = 0; j < TN; j++) rn[j] = Bs[cur][k][tc + j];
#pragma unroll
            for (int i = 0; i < TM; i++)
#pragma unroll
                for (int j = 0; j < TN; j++) acc[i][j] += rm[i] * rn[j];
        }
        __syncthreads();
    }

#pragma unroll
    for (int i = 0; i < TM; i++) {
        size_t row = (size_t)(by * BM + tr + i);
        float* Cp = C + row * N + bx * BN + tc;
        const float* Ap = (EPI == 2) ? (aux + row * N + bx * BN + tc) : nullptr;
#pragma unroll
        for (int j = 0; j < TN; j += 4) {
            float4 v = make_float4(acc[i][j], acc[i][j + 1], acc[i][j + 2], acc[i][j + 3]);
            if (EPI == 1) {
                v.x = v.x / (1.f + __expf(-v.x));
                v.y = v.y / (1.f + __expf(-v.y));
                v.z = v.z / (1.f + __expf(-v.z));
                v.w = v.w / (1.f + __expf(-v.w));
            }
            if (EPI == 2) {
                float4 a = *(const float4*)(Ap + j);
                v.x += a.x; v.y += a.y; v.z += a.z; v.w += a.w;
            }
            *(float4*)(Cp + j) = v;
        }
    }
}

// ---------------- launch ----------------
extern "C" void kernel_launch(void* const* d_in, const int* in_sizes, int n_in,
                              void* d_out, int out_size) {
    const float* patch   = (const float*)d_in[0];
    const float* pos     = (const float*)d_in[1];
    const float* w_gate  = (const float*)d_in[2];
    const float* w_in    = (const float*)d_in[3];
    const float* conv_w  = (const float*)d_in[4];
    const float* w_qkv   = (const float*)d_in[5];
    const float* w_intra = (const float*)d_in[6];
    const float* w_pool  = (const float*)d_in[7];
    const float* temp    = (const float*)d_in[8];
    const float* w_up    = (const float*)d_in[9];
    const float* w_down  = (const float*)d_in[10];
    const float* w_out   = (const float*)d_in[11];
    float* out = (float*)d_out;

    float *p_x, *p_xn, *p_t1, *p_t2, *p_qkv, *p_p0, *p_p1, *p_p2;
    cudaGetSymbolAddress((void**)&p_x,   g_x);
    cudaGetSymbolAddress((void**)&p_xn,  g_xn);
    cudaGetSymbolAddress((void**)&p_t1,  g_t1);
    cudaGetSymbolAddress((void**)&p_t2,  g_t2);
    cudaGetSymbolAddress((void**)&p_qkv, g_qkv);
    cudaGetSymbolAddress((void**)&p_p0,  g_p0);
    cudaGetSymbolAddress((void**)&p_p1,  g_p1);
    cudaGetSymbolAddress((void**)&p_p2,  g_p2);

    const int n4 = (int)(((size_t)T_ * D_) / 4);

    // 1. x1 = rmsnorm(patch + pos)
    k_add_pos_norm<<<T_, 256>>>(patch, pos, p_xn);

    // 2. gated MLP
    dim3 gBig(D_ / 128, T_ / 128);
    sgemm_nt<0><<<gBig, 256>>>(T_, D_, D_, p_xn, w_gate, nullptr, p_t1);
    sgemm_nt<0><<<gBig, 256>>>(T_, D_, D_, p_xn, w_in,   nullptr, p_t2);
    k_silu_mul<<<(n4 + 255) / 256, 256>>>(p_t1, p_t2, p_x, n4);

    // 3. depthwise causal conv + residual (in place on g_x)
    k_conv<<<dim3(P_, D_ / 256), 256>>>(p_x, conv_w);

    // 4. rmsnorm -> qkv -> attention -> out-proj -> residual+norm
    k_rmsnorm<<<T_, 256>>>(p_x, p_xn);
    sgemm_nt<0><<<dim3(3 * D_ / 128, T_ / 128), 256>>>(T_, 3 * D_, D_, p_xn, w_qkv, nullptr, p_qkv);
    k_attn<<<dim3(P_, NH_), 256>>>(p_qkv, p_t1);
    sgemm_nt<0><<<gBig, 256>>>(T_, D_, D_, p_t1, w_intra, nullptr, p_t2);
    k_add_norm<<<T_, 256>>>(p_x, p_t2, p_xn);     // x5

    // 5. attention pooling
    k_pool<<<P_, 256>>>(p_xn, w_pool, temp, p_p0);

    // 6. patch-level MLP + out proj + final norm
    dim3 gSmall(D_ / 128, P_ / 128);
    k_rmsnorm<<<P_, 256>>>(p_p0, p_p1);
    sgemm_nt<1><<<gSmall, 256>>>(P_, D_, D_, p_p1, w_up,   nullptr, p_p2);  // silu
    sgemm_nt<2><<<gSmall, 256>>>(P_, D_, D_, p_p2, w_down, p_p0,    p_p1);  // + pooled
    sgemm_nt<0><<<gSmall, 256>>>(P_, D_, D_, p_p1, w_out,  nullptr, p_p2);
    k_rmsnorm<<<P_, 256>>>(p_p2, out);
}

// round 3
// speedup vs baseline: 2.7366x; 2.7366x over previous
#include <cuda_runtime.h>
#include <stdint.h>
#include <math.h>

// ---------------- problem constants ----------------
#define B_    4
#define NP_   512
#define PS_   16
#define D_    1024
#define NH_   4
#define HD_   256
#define PH_   4
#define KW_   5
#define T_    (B_*NP_*PS_)        // 32768 tokens
#define P_    (B_*NP_)            // 2048 patches
#define EPS_  1.1920929e-7f

// ---------------- device scratch ----------------
__device__ float g_x  [(size_t)T_*D_];
__device__ float g_xn [(size_t)T_*D_];
__device__ float g_t1 [(size_t)T_*D_];
__device__ float g_t2 [(size_t)T_*D_];
__device__ float g_qkv[(size_t)T_*3*D_];
__device__ float g_p0 [(size_t)P_*D_];
__device__ float g_p1 [(size_t)P_*D_];
__device__ float g_p2 [(size_t)P_*D_];

// ================= HMMA bf16-split GEMM =================
// C[M,N] = A[M,K] @ Bw[N,K]^T, fp32 in/out, internally bf16 hi/lo split:
//   x = hi(x) + lo(x);  acc += hi_a*hi_b + hi_a*lo_b + lo_a*hi_b   (fp32 accum)
// Tile: 256x128 per CTA, 256 threads (8 warps = 4m x 2n, warp tile 64x64), BK=32.

#define BM_G 256
#define BN_G 128
#define BK_G 32
#define PITCH 80                       // bytes per 32-elt bf16 row (64B + 16B pad)
#define AHI_OFF 0
#define ALO_OFF (BM_G * PITCH)         // 20480
#define BHI_OFF (2 * BM_G * PITCH)     // 40960
#define BLO_OFF (BHI_OFF + BN_G * PITCH) // 51200
#define SSZ ((2 * BM_G + 2 * BN_G) * PITCH) // 61440 per stage
#define GEMM_SMEM (2 * SSZ)            // 122880

__device__ __forceinline__ void cvt_split(float x0, float x1,
                                          uint32_t& hw, uint32_t& lw) {
    uint32_t h;
    asm("cvt.rn.bf16x2.f32 %0, %1, %2;" : "=r"(h) : "f"(x1), "f"(x0));
    float h0 = __uint_as_float(h << 16);
    float h1 = __uint_as_float(h & 0xffff0000u);
    float l0 = x0 - h0, l1 = x1 - h1;
    asm("cvt.rn.bf16x2.f32 %0, %1, %2;" : "=r"(lw) : "f"(l1), "f"(l0));
    hw = h;
}

#define MMA_BF16(d, a, b) \
    asm volatile("mma.sync.aligned.m16n8k16.row.col.f32.bf16.bf16.f32 " \
        "{%0,%1,%2,%3},{%4,%5,%6,%7},{%8,%9},{%0,%1,%2,%3};" \
        : "+f"((d)[0]), "+f"((d)[1]), "+f"((d)[2]), "+f"((d)[3]) \
        : "r"((a)[0]), "r"((a)[1]), "r"((a)[2]), "r"((a)[3]), \
          "r"((b)[0]), "r"((b)[1]))

// EPI: 0 = store v; 1 = silu(v); 2 = v + aux; 3 = silu(aux) * v
template <int EPI>
__global__ __launch_bounds__(256, 1)
void hmma_gemm(int M, int N, int Kd,
               const float* __restrict__ A, const float* __restrict__ Bw,
               const float* __restrict__ aux, float* __restrict__ C) {
    extern __shared__ uint8_t sm[];
    const int tid = threadIdx.x;
    const int warp = tid >> 5, lane = tid & 31;
    const int qr = lane >> 2, qc = lane & 3;
    const int wm = warp & 3;           // 0..3 -> m offset 64*wm
    const int wn = warp >> 2;          // 0..1 -> n offset 64*wn
    const int bx = blockIdx.x, by = blockIdx.y;
    const int rowbase = tid >> 3, c4 = tid & 7;

    float acc[4][8][4];
#pragma unroll
    for (int i = 0; i < 4; i++)
#pragma unroll
        for (int j = 0; j < 8; j++)
#pragma unroll
            for (int r = 0; r < 4; r++) acc[i][j][r] = 0.f;

    const float* Ag = A  + (size_t)(by * BM_G + rowbase) * Kd + c4 * 4;
    const float* Bg = Bw + (size_t)(bx * BN_G + rowbase) * Kd + c4 * 4;

    float4 ra[8], rb[4];
    const int nk = Kd / BK_G;

    // ---- prologue: chunk 0 -> stage 0
#pragma unroll
    for (int i = 0; i < 8; i++) ra[i] = *(const float4*)(Ag + (size_t)(32 * i) * Kd);
#pragma unroll
    for (int i = 0; i < 4; i++) rb[i] = *(const float4*)(Bg + (size_t)(32 * i) * Kd);
    {
        uint8_t* st = sm;
#pragma unroll
        for (int i = 0; i < 8; i++) {
            uint32_t h0, l0, h1, l1;
            cvt_split(ra[i].x, ra[i].y, h0, l0);
            cvt_split(ra[i].z, ra[i].w, h1, l1);
            int off = (rowbase + 32 * i) * PITCH + c4 * 8;
            *(uint2*)(st + AHI_OFF + off) = make_uint2(h0, h1);
            *(uint2*)(st + ALO_OFF + off) = make_uint2(l0, l1);
        }
#pragma unroll
        for (int i = 0; i < 4; i++) {
            uint32_t h0, l0, h1, l1;
            cvt_split(rb[i].x, rb[i].y, h0, l0);
            cvt_split(rb[i].z, rb[i].w, h1, l1);
            int off = (rowbase + 32 * i) * PITCH + c4 * 8;
            *(uint2*)(st + BHI_OFF + off) = make_uint2(h0, h1);
            *(uint2*)(st + BLO_OFF + off) = make_uint2(l0, l1);
        }
    }
    __syncthreads();

    for (int kt = 0; kt < nk; kt++) {
        const int cur = kt & 1;
        const bool more = (kt + 1) < nk;
        if (more) {
            const int ko = (kt + 1) * BK_G;
#pragma unroll
            for (int i = 0; i < 8; i++) ra[i] = *(const float4*)(Ag + (size_t)(32 * i) * Kd + ko);
#pragma unroll
            for (int i = 0; i < 4; i++) rb[i] = *(const float4*)(Bg + (size_t)(32 * i) * Kd + ko);
        }

        // ---- compute current stage
        {
            const uint8_t* st = sm + cur * SSZ;
#pragma unroll
            for (int ks = 0; ks < 2; ks++) {
                const int kb = qc * 4 + ks * 32;
                uint32_t ah[4][4], al[4][4];
#pragma unroll
                for (int mf = 0; mf < 4; mf++) {
                    const int r = wm * 64 + mf * 16 + qr;
                    const uint8_t* pH = st + AHI_OFF + r * PITCH + kb;
                    const uint8_t* pL = st + ALO_OFF + r * PITCH + kb;
                    ah[mf][0] = *(const uint32_t*)(pH);
                    ah[mf][1] = *(const uint32_t*)(pH + 8 * PITCH);
                    ah[mf][2] = *(const uint32_t*)(pH + 16);
                    ah[mf][3] = *(const uint32_t*)(pH + 8 * PITCH + 16);
                    al[mf][0] = *(const uint32_t*)(pL);
                    al[mf][1] = *(const uint32_t*)(pL + 8 * PITCH);
                    al[mf][2] = *(const uint32_t*)(pL + 16);
                    al[mf][3] = *(const uint32_t*)(pL + 8 * PITCH + 16);
                }
#pragma unroll
                for (int nf = 0; nf < 8; nf++) {
                    const int rn = wn * 64 + nf * 8 + qr;
                    const uint8_t* pBH = st + BHI_OFF + rn * PITCH + kb;
                    const uint8_t* pBL = st + BLO_OFF + rn * PITCH + kb;
                    uint32_t bh[2], bl[2];
                    bh[0] = *(const uint32_t*)(pBH);
                    bh[1] = *(const uint32_t*)(pBH + 16);
                    bl[0] = *(const uint32_t*)(pBL);
                    bl[1] = *(const uint32_t*)(pBL + 16);
#pragma unroll
                    for (int mf = 0; mf < 4; mf++) {
                        MMA_BF16(acc[mf][nf], ah[mf], bh);
                        MMA_BF16(acc[mf][nf], ah[mf], bl);
                        MMA_BF16(acc[mf][nf], al[mf], bh);
                    }
                }
            }
        }

        if (more) {
            uint8_t* st = sm + ((kt + 1) & 1) * SSZ;
#pragma unroll
            for (int i = 0; i < 8; i++) {
                uint32_t h0, l0, h1, l1;
                cvt_split(ra[i].x, ra[i].y, h0, l0);
                cvt_split(ra[i].z, ra[i].w, h1, l1);
                int off = (rowbase + 32 * i) * PITCH + c4 * 8;
                *(uint2*)(st + AHI_OFF + off) = make_uint2(h0, h1);
                *(uint2*)(st + ALO_OFF + off) = make_uint2(l0, l1);
            }
#pragma unroll
            for (int i = 0; i < 4; i++) {
                uint32_t h0, l0, h1, l1;
                cvt_split(rb[i].x, rb[i].y, h0, l0);
                cvt_split(rb[i].z, rb[i].w, h1, l1);
                int off = (rowbase + 32 * i) * PITCH + c4 * 8;
                *(uint2*)(st + BHI_OFF + off) = make_uint2(h0, h1);
                *(uint2*)(st + BLO_OFF + off) = make_uint2(l0, l1);
            }
            __syncthreads();
        }
    }

    // ---- epilogue
    const int row0 = by * BM_G + wm * 64;
    const int col0 = bx * BN_G + wn * 64;
#pragma unroll
    for (int mf = 0; mf < 4; mf++) {
#pragma unroll
        for (int nf = 0; nf < 8; nf++) {
            const int r = row0 + mf * 16 + qr;
            const int c = col0 + nf * 8 + qc * 2;
            float* p0 = C + (size_t)r * N + c;
            float* p1 = C + (size_t)(r + 8) * N + c;
            float v0 = acc[mf][nf][0], v1 = acc[mf][nf][1];
            float v2 = acc[mf][nf][2], v3 = acc[mf][nf][3];
            if (EPI == 1) {
                v0 = v0 / (1.f + __expf(-v0)); v1 = v1 / (1.f + __expf(-v1));
                v2 = v2 / (1.f + __expf(-v2)); v3 = v3 / (1.f + __expf(-v3));
            }
            if (EPI == 2) {
                const float* a0 = aux + (size_t)r * N + c;
                const float* a1 = aux + (size_t)(r + 8) * N + c;
                v0 += a0[0]; v1 += a0[1]; v2 += a1[0]; v3 += a1[1];
            }
            if (EPI == 3) {
                const float* a0 = aux + (size_t)r * N + c;
                const float* a1 = aux + (size_t)(r + 8) * N + c;
                float g0 = a0[0], g1 = a0[1], g2 = a1[0], g3 = a1[1];
                v0 *= g0 / (1.f + __expf(-g0)); v1 *= g1 / (1.f + __expf(-g1));
                v2 *= g2 / (1.f + __expf(-g2)); v3 *= g3 / (1.f + __expf(-g3));
            }
            *(float2*)p0 = make_float2(v0, v1);
            *(float2*)p1 = make_float2(v2, v3);
        }
    }
}

// ================= aux kernels (passed in R1) =================
__device__ __forceinline__ float warp_sum(float v) {
#pragma unroll
    for (int o = 16; o; o >>= 1) v += __shfl_down_sync(0xffffffffu, v, o);
    return v;
}
__device__ __forceinline__ float block_sum_256(float v, float* red) {
    int lane = threadIdx.x & 31, w = threadIdx.x >> 5;
    v = warp_sum(v);
    if (lane == 0) red[w] = v;
    __syncthreads();
    if (w == 0) {
        float x = (lane < 8) ? red[lane] : 0.f;
        x = warp_sum(x);
        if (lane == 0) red[0] = x;
    }
    __syncthreads();
    return red[0];
}

__global__ void k_add_pos_norm(const float* __restrict__ x,
                               const float* __restrict__ pos,
                               float* __restrict__ out) {
    __shared__ float red[8];
    int row = blockIdx.x, t = threadIdx.x;
    float4 a = ((const float4*)(x + (size_t)row * D_))[t];
    float4 b = ((const float4*)(pos + (size_t)(row & (PS_ - 1)) * D_))[t];
    a.x += b.x; a.y += b.y; a.z += b.z; a.w += b.w;
    float tot = block_sum_256(a.x*a.x + a.y*a.y + a.z*a.z + a.w*a.w, red);
    float s = rsqrtf(tot * (1.0f / D_) + EPS_);
    ((float4*)(out + (size_t)row * D_))[t] = make_float4(a.x*s, a.y*s, a.z*s, a.w*s);
}

__global__ void k_rmsnorm(const float* __restrict__ x, float* __restrict__ out) {
    __shared__ float red[8];
    int row = blockIdx.x, t = threadIdx.x;
    float4 a = ((const float4*)(x + (size_t)row * D_))[t];
    float tot = block_sum_256(a.x*a.x + a.y*a.y + a.z*a.z + a.w*a.w, red);
    float s = rsqrtf(tot * (1.0f / D_) + EPS_);
    ((float4*)(out + (size_t)row * D_))[t] = make_float4(a.x*s, a.y*s, a.z*s, a.w*s);
}

__global__ void k_conv(float* __restrict__ x, const float* __restrict__ w) {
    int patch = blockIdx.x;
    int c = blockIdx.y * blockDim.x + threadIdx.x;
    float wk[KW_];
#pragma unroll
    for (int k = 0; k < KW_; k++) wk[k] = w[c * KW_ + k];
    size_t base = (size_t)patch * PS_ * D_ + c;
    float v[PS_];
#pragma unroll
    for (int p = 0; p < PS_; p++) v[p] = x[base + (size_t)p * D_];
#pragma unroll
    for (int p = 0; p < PS_; p++) {
        float acc = v[p];
#pragma unroll
        for (int k = 0; k < KW_; k++) {
            int src = p + k - (KW_ - 1);
            if (src >= 0) acc += v[src] * wk[k];
        }
        x[base + (size_t)p * D_] = acc;
    }
}

__global__ void k_attn(const float* __restrict__ qkv, float* __restrict__ sa) {
    __shared__ float bufA[PS_ * HD_];
    __shared__ float bufK[HD_ * (PS_ + 1)];
    __shared__ float S[PS_][PS_ + 1];
    int patch = blockIdx.x, h = blockIdx.y, t = threadIdx.x;

    for (int i = t; i < PS_ * HD_; i += 256) {
        int p = i >> 8, d = i & (HD_ - 1);
        size_t base = ((size_t)(patch * PS_ + p)) * (3 * D_) + (size_t)h * HD_;
        bufA[p * HD_ + d] = qkv[base + d];
        bufK[d * (PS_ + 1) + p] = qkv[base + D_ + d];
    }
    __syncthreads();
    {
        int i = t >> 4, j = t & 15;
        float acc = 0.f;
#pragma unroll 8
        for (int d = 0; d < HD_; d++)
            acc += bufA[i * HD_ + d] * bufK[d * (PS_ + 1) + j];
        S[i][j] = acc * 0.0625f;
    }
    __syncthreads();
    for (int i = t; i < PS_ * HD_; i += 256) {
        int p = i >> 8, d = i & (HD_ - 1);
        size_t base = ((size_t)(patch * PS_ + p)) * (3 * D_) + (size_t)h * HD_;
        bufA[p * HD_ + d] = qkv[base + 2 * D_ + d];
    }
    if (t < PS_) {
        float lv[PS_], m = -1e30f;
#pragma unroll
        for (int j = 0; j < PS_; j++) { lv[j] = S[t][j]; m = fmaxf(m, lv[j]); }
        float s = 0.f;
#pragma unroll
        for (int j = 0; j < PS_; j++) { lv[j] = __expf(lv[j] - m); s += lv[j]; }
        float inv = 1.f / s;
#pragma unroll
        for (int j = 0; j < PS_; j++) S[t][j] = lv[j] * inv;
    }
    __syncthreads();
    {
        int i = t >> 4, dc = t & 15;
        float acc[16];
#pragma unroll
        for (int r = 0; r < 16; r++) acc[r] = 0.f;
#pragma unroll
        for (int j = 0; j < PS_; j++) {
            float s = S[i][j];
#pragma unroll
            for (int r = 0; r < 16; r++)
                acc[r] += s * bufA[j * HD_ + dc + (r << 4)];
        }
        size_t ob = ((size_t)(patch * PS_ + i)) * D_ + (size_t)h * HD_ + dc;
#pragma unroll
        for (int r = 0; r < 16; r++) sa[ob + (r << 4)] = acc[r];
    }
}

__global__ void k_pool(const float* __restrict__ x5,
                       const float* __restrict__ wpool,
                       const float* __restrict__ temp,
                       float* __restrict__ out) {
    __shared__ float swp[PH_ * D_];
    __shared__ float slog[PH_][PS_];
    int patch = blockIdx.x, t = threadIdx.x;
    for (int i = t; i < PH_ * D_; i += 256) swp[i] = wpool[i];
    __syncthreads();

    int w = t >> 5, lane = t & 31;
    for (int p = w; p < PS_; p += 8) {
        const float* xr = x5 + ((size_t)patch * PS_ + p) * D_;
        float a0 = 0, a1 = 0, a2 = 0, a3 = 0;
        for (int d = lane; d < D_; d += 32) {
            float xv = xr[d];
            a0 += xv * swp[d];
            a1 += xv * swp[D_ + d];
            a2 += xv * swp[2 * D_ + d];
            a3 += xv * swp[3 * D_ + d];
        }
        a0 = warp_sum(a0); a1 = warp_sum(a1); a2 = warp_sum(a2); a3 = warp_sum(a3);
        if (lane == 0) { slog[0][p] = a0; slog[1][p] = a1; slog[2][p] = a2; slog[3][p] = a3; }
    }
    __syncthreads();
    if (t < PH_) {
        float inv = 1.f / fmaxf(temp[0], 0.01f);
        float lv[PS_], m = -1e30f;
#pragma unroll
        for (int p = 0; p < PS_; p++) { lv[p] = slog[t][p] * inv; m = fmaxf(m, lv[p]); }
        float s = 0.f;
#pragma unroll
        for (int p = 0; p < PS_; p++) { lv[p] = __expf(lv[p] - m); s += lv[p]; }
        float is = 1.f / s;
#pragma unroll
        for (int p = 0; p < PS_; p++) slog[t][p] = lv[p] * is;
    }
    __syncthreads();
    int dd = t * 4;
    int h = dd >> 8;
    float4 acc = make_float4(0, 0, 0, 0);
#pragma unroll
    for (int p = 0; p < PS_; p++) {
        float wg = slog[h][p];
        float4 xv = *(const float4*)(x5 + ((size_t)patch * PS_ + p) * D_ + dd);
        acc.x += wg * xv.x; acc.y += wg * xv.y; acc.z += wg * xv.z; acc.w += wg * xv.w;
    }
    *(float4*)(out + (size_t)patch * D_ + dd) = acc;
}

// ================= launch =================
extern "C" void kernel_launch(void* const* d_in, const int* in_sizes, int n_in,
                              void* d_out, int out_size) {
    const float* patch   = (const float*)d_in[0];
    const float* pos     = (const float*)d_in[1];
    const float* w_gate  = (const float*)d_in[2];
    const float* w_in    = (const float*)d_in[3];
    const float* conv_w  = (const float*)d_in[4];
    const float* w_qkv   = (const float*)d_in[5];
    const float* w_intra = (const float*)d_in[6];
    const float* w_pool  = (const float*)d_in[7];
    const float* temp    = (const float*)d_in[8];
    const float* w_up    = (const float*)d_in[9];
    const float* w_down  = (const float*)d_in[10];
    const float* w_out   = (const float*)d_in[11];
    float* out = (float*)d_out;

    float *p_x, *p_xn, *p_t1, *p_t2, *p_qkv, *p_p0, *p_p1, *p_p2;
    cudaGetSymbolAddress((void**)&p_x,   g_x);
    cudaGetSymbolAddress((void**)&p_xn,  g_xn);
    cudaGetSymbolAddress((void**)&p_t1,  g_t1);
    cudaGetSymbolAddress((void**)&p_t2,  g_t2);
    cudaGetSymbolAddress((void**)&p_qkv, g_qkv);
    cudaGetSymbolAddress((void**)&p_p0,  g_p0);
    cudaGetSymbolAddress((void**)&p_p1,  g_p1);
    cudaGetSymbolAddress((void**)&p_p2,  g_p2);

    cudaFuncSetAttribute(hmma_gemm<0>, cudaFuncAttributeMaxDynamicSharedMemorySize, GEMM_SMEM);
    cudaFuncSetAttribute(hmma_gemm<1>, cudaFuncAttributeMaxDynamicSharedMemorySize, GEMM_SMEM);
    cudaFuncSetAttribute(hmma_gemm<2>, cudaFuncAttributeMaxDynamicSharedMemorySize, GEMM_SMEM);
    cudaFuncSetAttribute(hmma_gemm<3>, cudaFuncAttributeMaxDynamicSharedMemorySize, GEMM_SMEM);

    dim3 gBig(D_ / BN_G, T_ / BM_G);          // (8, 128)
    dim3 gQkv(3 * D_ / BN_G, T_ / BM_G);      // (24, 128)
    dim3 gSm(D_ / BN_G, P_ / BM_G);           // (8, 8)

    // 1. x1 = rmsnorm(patch + pos)
    k_add_pos_norm<<<T_, 256>>>(patch, pos, p_xn);

    // 2. gated MLP: x = silu(x1@Wg^T) * (x1@Wi^T)
    hmma_gemm<0><<<gBig, 256, GEMM_SMEM>>>(T_, D_, D_, p_xn, w_gate, nullptr, p_t1);
    hmma_gemm<3><<<gBig, 256, GEMM_SMEM>>>(T_, D_, D_, p_xn, w_in, p_t1, p_x);

    // 3. depthwise causal conv + residual (in place)
    k_conv<<<dim3(P_, D_ / 256), 256>>>(p_x, conv_w);

    // 4. attention block
    k_rmsnorm<<<T_, 256>>>(p_x, p_xn);
    hmma_gemm<0><<<gQkv, 256, GEMM_SMEM>>>(T_, 3 * D_, D_, p_xn, w_qkv, nullptr, p_qkv);
    k_attn<<<dim3(P_, NH_), 256>>>(p_qkv, p_t1);
    hmma_gemm<2><<<gBig, 256, GEMM_SMEM>>>(T_, D_, D_, p_t1, w_intra, p_x, p_t2);
    k_rmsnorm<<<T_, 256>>>(p_t2, p_xn);       // x5

    // 5. attention pooling
    k_pool<<<P_, 256>>>(p_xn, w_pool, temp, p_p0);

    // 6. patch-level MLP + out proj + final norm
    k_rmsnorm<<<P_, 256>>>(p_p0, p_p1);
    hmma_gemm<1><<<gSm, 256, GEMM_SMEM>>>(P_, D_, D_, p_p1, w_up, nullptr, p_p2);
    hmma_gemm<2><<<gSm, 256, GEMM_SMEM>>>(P_, D_, D_, p_p2, w_down, p_p0, p_p1);
    hmma_gemm<0><<<gSm, 256, GEMM_SMEM>>>(P_, D_, D_, p_p1, w_out, nullptr, p_p2);
    k_rmsnorm<<<P_, 256>>>(p_p2, out);
}